// round 1
// baseline (speedup 1.0000x reference)
#include <cuda_runtime.h>
#include <math.h>

#define Bc 8
#define Nn 4096
#define Dd 768
#define Hh 12
#define dh 64
#define Mrows (Bc*Nn)      /* 32768 */
#define QKVC  (3*Dd)       /* 2304  */

// Scratch (allocation-free rule: device globals)
__device__ float g_qkv[(size_t)Mrows * QKVC];    // 302 MB
__device__ float g_attn[Bc*Hh*dh*dh];            // 1.5 MB
__device__ float g_oattn[(size_t)Mrows * Dd];    // 100 MB

// ---------------------------------------------------------------------------
// 128x128x16 register-blocked SGEMM, row-major A(MxK) * B(KxN) = C(MxN) (+bias)
// Requires M%128==0, N%128==0, K%16==0 (true for all our shapes).
// ---------------------------------------------------------------------------
__global__ __launch_bounds__(256) void sgemm128(
    const float* __restrict__ A, const float* __restrict__ B,
    float* __restrict__ C, int M, int N, int K,
    const float* __restrict__ bias)
{
    __shared__ float As[16][132];  // A tile transposed, padded
    __shared__ float Bs[16][128];
    const int tid  = threadIdx.x;
    const int tx   = tid & 15;
    const int ty   = tid >> 4;
    const int row0 = blockIdx.y * 128;
    const int col0 = blockIdx.x * 128;

    const int a_r = tid >> 2;          // 0..63
    const int a_c = (tid & 3) << 2;    // 0,4,8,12
    const int b_r = tid >> 5;          // 0..7
    const int b_c = (tid & 31) << 2;   // 0..124

    float acc[8][8];
    #pragma unroll
    for (int i = 0; i < 8; i++)
        #pragma unroll
        for (int j = 0; j < 8; j++) acc[i][j] = 0.f;

    for (int k0 = 0; k0 < K; k0 += 16) {
        #pragma unroll
        for (int rr = 0; rr < 128; rr += 64) {
            float4 v = *(const float4*)(A + (size_t)(row0 + a_r + rr) * K + k0 + a_c);
            As[a_c + 0][a_r + rr] = v.x;
            As[a_c + 1][a_r + rr] = v.y;
            As[a_c + 2][a_r + rr] = v.z;
            As[a_c + 3][a_r + rr] = v.w;
        }
        #pragma unroll
        for (int rr = 0; rr < 16; rr += 8) {
            *(float4*)&Bs[b_r + rr][b_c] =
                *(const float4*)(B + (size_t)(k0 + b_r + rr) * N + col0 + b_c);
        }
        __syncthreads();
        #pragma unroll
        for (int kk = 0; kk < 16; kk++) {
            float ra[8], rb[8];
            *(float4*)&ra[0] = *(const float4*)&As[kk][ty * 8];
            *(float4*)&ra[4] = *(const float4*)&As[kk][ty * 8 + 4];
            *(float4*)&rb[0] = *(const float4*)&Bs[kk][tx * 8];
            *(float4*)&rb[4] = *(const float4*)&Bs[kk][tx * 8 + 4];
            #pragma unroll
            for (int i = 0; i < 8; i++)
                #pragma unroll
                for (int j = 0; j < 8; j++)
                    acc[i][j] = fmaf(ra[i], rb[j], acc[i][j]);
        }
        __syncthreads();
    }

    #pragma unroll
    for (int i = 0; i < 8; i++) {
        const int r = row0 + ty * 8 + i;
        #pragma unroll
        for (int j = 0; j < 8; j += 4) {
            const int c = col0 + tx * 8 + j;
            float4 v;
            v.x = acc[i][j + 0]; v.y = acc[i][j + 1];
            v.z = acc[i][j + 2]; v.w = acc[i][j + 3];
            if (bias) { v.x += bias[c]; v.y += bias[c + 1]; v.z += bias[c + 2]; v.w += bias[c + 3]; }
            *(float4*)(C + (size_t)r * N + c) = v;
        }
    }
}

// ---------------------------------------------------------------------------
// Fused: raw cross-covariance (k^T q over n) + column L2 norms (normalization
// factors out of the reduction) + temperature + softmax.  One CTA per (b,h).
// ---------------------------------------------------------------------------
__global__ __launch_bounds__(256) void attn_kernel(const float* __restrict__ temp)
{
    const int bh = blockIdx.x;
    const int b  = bh / Hh, h = bh % Hh;
    const int tid = threadIdx.x;
    const int tx = tid & 15, ty = tid >> 4;

    __shared__ float Qs[64][68];
    __shared__ float Ks[64][68];
    __shared__ float ps[256];
    __shared__ float normQ[64], normK[64];

    const size_t rowbase = (size_t)b * Nn;
    const int qoff = h * dh;
    const int koff = Dd + h * dh;

    float acc[4][4];
    #pragma unroll
    for (int i = 0; i < 4; i++)
        #pragma unroll
        for (int j = 0; j < 4; j++) acc[i][j] = 0.f;
    float pssq = 0.f;

    const int lr = tid >> 4;          // 0..15 row within load pass
    const int lc = (tid & 15) << 2;   // float4 column
    const int scol  = tid & 127;      // ssq column (0..63 Q, 64..127 K)
    const int shalf = (tid >> 7) * 32;

    for (int n0 = 0; n0 < Nn; n0 += 64) {
        #pragma unroll
        for (int pp = 0; pp < 64; pp += 16) {
            const size_t grow = (rowbase + n0 + pp + lr) * QKVC;
            *(float4*)&Qs[pp + lr][lc] = *(const float4*)(g_qkv + grow + qoff + lc);
            *(float4*)&Ks[pp + lr][lc] = *(const float4*)(g_qkv + grow + koff + lc);
        }
        __syncthreads();
        #pragma unroll 4
        for (int n = 0; n < 64; n++) {
            float rq[4], rk[4];
            *(float4*)rq = *(const float4*)&Qs[n][tx * 4];
            *(float4*)rk = *(const float4*)&Ks[n][ty * 4];
            #pragma unroll
            for (int i = 0; i < 4; i++)
                #pragma unroll
                for (int j = 0; j < 4; j++)
                    acc[i][j] = fmaf(rk[i], rq[j], acc[i][j]);
        }
        // per-column sum of squares (for L2 norms), factored out of the GEMM
        {
            const float* colp = (scol < 64) ? &Qs[0][scol] : &Ks[0][scol - 64];
            #pragma unroll
            for (int n = 0; n < 32; n++) {
                const float v = colp[(size_t)(shalf + n) * 68];
                pssq = fmaf(v, v, pssq);
            }
        }
        __syncthreads();
    }

    ps[tid] = pssq;
    __syncthreads();
    if (tid < 128) {
        const float s  = ps[tid] + ps[tid + 128];
        const float nv = fmaxf(sqrtf(s), 1e-12f);
        if (tid < 64) normQ[tid] = nv; else normK[tid - 64] = nv;
    }
    __syncthreads();

    const float tv = temp[h];
    #pragma unroll
    for (int i = 0; i < 4; i++)
        #pragma unroll
        for (int j = 0; j < 4; j++)
            Qs[ty * 4 + i][tx * 4 + j] =
                acc[i][j] * tv / (normK[ty * 4 + i] * normQ[tx * 4 + j]);
    __syncthreads();

    // softmax over q (last axis), one thread per p row
    if (tid < 64) {
        const int p = tid;
        float m = -1e30f;
        for (int q = 0; q < 64; q++) m = fmaxf(m, Qs[p][q]);
        float s = 0.f;
        for (int q = 0; q < 64; q++) s += expf(Qs[p][q] - m);
        const float inv = 1.f / s;
        float* op = g_attn + (size_t)bh * 4096 + p * 64;
        for (int q = 0; q < 64; q++) op[q] = expf(Qs[p][q] - m) * inv;
    }
}

// ---------------------------------------------------------------------------
// out[b,h,n,q] = sum_p v[b,h,n,p] * attn[b,h,p,q], written back into
// (b*N+n, h*64+q) row-major layout for the final GEMM.
// Grid: (96 bh, 64 n-tiles of 64)
// ---------------------------------------------------------------------------
__global__ __launch_bounds__(256) void av_kernel()
{
    const int bh = blockIdx.x;
    const int nt = blockIdx.y;
    const int b  = bh / Hh, h = bh % Hh;
    const int tid = threadIdx.x;
    const int tx = tid & 15, ty = tid >> 4;

    __shared__ float At[64][68];
    __shared__ float Vs[64][68];

    {   // load attn tile (4096 floats)
        const float* ap = g_attn + (size_t)bh * 4096;
        #pragma unroll
        for (int pp = 0; pp < 4; pp++) {
            const int idx = pp * 1024 + tid * 4;
            *(float4*)&At[idx >> 6][idx & 63] = *(const float4*)(ap + idx);
        }
    }
    const int lr = tid >> 4, lc = (tid & 15) << 2;
    const int voff = 2 * Dd + h * dh;
    const size_t rowbase = (size_t)b * Nn + nt * 64;
    #pragma unroll
    for (int pp = 0; pp < 64; pp += 16)
        *(float4*)&Vs[pp + lr][lc] =
            *(const float4*)(g_qkv + (rowbase + pp + lr) * QKVC + voff + lc);
    __syncthreads();

    float acc[4][4];
    #pragma unroll
    for (int i = 0; i < 4; i++)
        #pragma unroll
        for (int j = 0; j < 4; j++) acc[i][j] = 0.f;

    #pragma unroll 8
    for (int p = 0; p < 64; p++) {
        float ra[4];
        *(float4*)ra = *(const float4*)&At[p][tx * 4];
        float rv[4];
        #pragma unroll
        for (int i = 0; i < 4; i++) rv[i] = Vs[ty * 4 + i][p];
        #pragma unroll
        for (int i = 0; i < 4; i++)
            #pragma unroll
            for (int j = 0; j < 4; j++)
                acc[i][j] = fmaf(rv[i], ra[j], acc[i][j]);
    }

    #pragma unroll
    for (int i = 0; i < 4; i++) {
        const size_t r = rowbase + ty * 4 + i;
        float4 v;
        v.x = acc[i][0]; v.y = acc[i][1]; v.z = acc[i][2]; v.w = acc[i][3];
        *(float4*)(g_oattn + r * Dd + h * dh + tx * 4) = v;
    }
}

// ---------------------------------------------------------------------------
extern "C" void kernel_launch(void* const* d_in, const int* in_sizes, int n_in,
                              void* d_out, int out_size)
{
    const float* x     = (const float*)d_in[0];
    const float* Wqkv  = (const float*)d_in[1];
    const float* temp  = (const float*)d_in[2];
    const float* Wout  = (const float*)d_in[3];
    const float* bout  = (const float*)d_in[4];
    float* out = (float*)d_out;

    float* qkv = nullptr;
    float* oattn = nullptr;
    cudaGetSymbolAddress((void**)&qkv, g_qkv);
    cudaGetSymbolAddress((void**)&oattn, g_oattn);

    dim3 blk(256);
    // 1) qkv = x @ Wqkv
    sgemm128<<<dim3(QKVC / 128, Mrows / 128), blk>>>(x, Wqkv, qkv, Mrows, QKVC, Dd, nullptr);
    // 2) fused normalize + cross-covariance + temperature + softmax
    attn_kernel<<<dim3(Bc * Hh), blk>>>(temp);
    // 3) out = v @ attn  (into GEMM-friendly layout)
    av_kernel<<<dim3(Bc * Hh, Nn / 64), blk>>>();
    // 4) final projection + bias
    sgemm128<<<dim3(Dd / 128, Mrows / 128), blk>>>(oattn, Wout, out, Mrows, Dd, Dd, bout);
}

// round 3
// speedup vs baseline: 2.2980x; 2.2980x over previous
#include <cuda_runtime.h>
#include <cuda_bf16.h>
#include <math.h>
#include <stdint.h>

#define Bc 8
#define Nn 4096
#define Dd 768
#define Hh 12
#define dh 64
#define Mrows (Bc*Nn)      /* 32768 */
#define QKVC  (3*Dd)       /* 2304  */
#define GK    Dd           /* GEMM K = 768 */

// ---------------- scratch (device globals; allocation-free rule) -----------
__device__ float g_qkv[(size_t)Mrows * QKVC];          // 302 MB
__device__ float g_attn[Bc*Hh*dh*dh];                  // 1.5 MB
__device__ float g_oattn[(size_t)Mrows * Dd];          // 100 MB
__device__ __nv_bfloat16 g_xh[(size_t)Mrows*Dd],  g_xl[(size_t)Mrows*Dd];
__device__ __nv_bfloat16 g_wh[(size_t)QKVC*Dd],   g_wl[(size_t)QKVC*Dd];   // [N,K]
__device__ __nv_bfloat16 g_woh[(size_t)Dd*Dd],    g_wol[(size_t)Dd*Dd];
__device__ __nv_bfloat16 g_oh[(size_t)Mrows*Dd],  g_ol[(size_t)Mrows*Dd];

// ---------------- arch feature gate -----------------------------------------
#if defined(__CUDA_ARCH_FEAT_SM103_ALL) || defined(__CUDA_ARCH_FEAT_SM100_ALL) || defined(__CUDA_ARCH_FEAT_SM101_ALL)
#define HAS_TCG 1
#else
#define HAS_TCG 0
#endif

// ---------------- common helpers --------------------------------------------
__device__ __forceinline__ uint32_t smem_u32(const void* p){
    uint32_t a;
    asm("{ .reg .u64 t; cvta.to.shared.u64 t, %1; cvt.u32.u64 %0, t; }" : "=r"(a) : "l"(p));
    return a;
}
__device__ __forceinline__ uint32_t swz(uint32_t o){ return o ^ ((o >> 3) & 0x70); }

// ---------------- GEMM tile geometry ----------------------------------------
#define MT 128
#define NT 128
#define KCH 64
#define NCH (GK/KCH)            /* 12 */
#define A_BYTES (MT*128)        /* 16384 */
#define B_BYTES (NT*128)        /* 16384 */
#define STAGE_BYTES (2*A_BYTES + 2*B_BYTES)  /* 65536 */
#define SM_TILE0 1024
#define GEMM_SMEM (SM_TILE0 + 2*STAGE_BYTES) /* 132096 */

#if HAS_TCG
// ---------------- tcgen05 helpers (arch-specific pass only) -----------------
__device__ __forceinline__ uint32_t elect1(){
    uint32_t p;
    asm volatile("{\n\t.reg .pred p;\n\telect.sync _|p, 0xFFFFFFFF;\n\tselp.b32 %0, 1, 0, p;\n\t}" : "=r"(p));
    return p;
}
static constexpr uint64_t DESC_BASE_SW128 =
    (uint64_t(2) << 61) | (uint64_t(1) << 46) | (uint64_t(64) << 32) | (uint64_t(1) << 16);
#define MK_DESC(a) (DESC_BASE_SW128 | ((uint64_t)((a) >> 4) & 0x3FFF))
// idesc: F32 accum, BF16 a/b, M=128, N=128
#define GEMM_IDESC 0x8200490u

__device__ __forceinline__ void mma_bf16_ss(uint32_t d, uint64_t a, uint64_t b, uint32_t en){
    asm volatile(
        "{\n\t.reg .pred p;\n\tsetp.ne.u32 p, %3, 0;\n\t"
        "tcgen05.mma.cta_group::1.kind::f16 [%0], %1, %2, %4, {%5,%5,%5,%5}, p;\n\t}"
        :: "r"(d), "l"(a), "l"(b), "r"(en), "r"(GEMM_IDESC), "r"(0u) : "memory");
}
__device__ __forceinline__ void tc_commit(uint32_t mbar){
    asm volatile("tcgen05.commit.cta_group::1.mbarrier::arrive::one.shared::cluster.b64 [%0];"
                 :: "r"(mbar) : "memory");
}
__device__ __forceinline__ void mbar_init(uint32_t mbar, uint32_t cnt){
    asm volatile("mbarrier.init.shared.b64 [%0], %1;" :: "r"(mbar), "r"(cnt) : "memory");
}
__device__ __forceinline__ void mbar_wait(uint32_t mbar, uint32_t parity){
    asm volatile(
        "{\n\t.reg .pred P;\n\tWL_%=:\n\t"
        "mbarrier.try_wait.parity.acquire.cta.shared::cta.b64 P, [%0], %1, 0x989680;\n\t"
        "@P bra.uni WD_%=;\n\tbra.uni WL_%=;\n\tWD_%=:\n\t}"
        :: "r"(mbar), "r"(parity) : "memory");
}
#define FENCE_ASYNC()  asm volatile("fence.proxy.async.shared::cta;" ::: "memory")
#define TC_FENCE_AFTER()  asm volatile("tcgen05.fence::after_thread_sync;" ::: "memory")
#define TC_FENCE_BEFORE() asm volatile("tcgen05.fence::before_thread_sync;" ::: "memory")
#define TC_WAIT_LD() asm volatile("tcgen05.wait::ld.sync.aligned;" ::: "memory")

#define LDTM32(r, addr) \
    asm volatile( \
        "tcgen05.ld.sync.aligned.32x32b.x32.b32 " \
        "{%0, %1, %2, %3, %4, %5, %6, %7, " \
        " %8, %9, %10, %11, %12, %13, %14, %15, " \
        " %16, %17, %18, %19, %20, %21, %22, %23, " \
        " %24, %25, %26, %27, %28, %29, %30, %31}, [%32];" \
        : "=r"((r)[0]),  "=r"((r)[1]),  "=r"((r)[2]),  "=r"((r)[3]), \
          "=r"((r)[4]),  "=r"((r)[5]),  "=r"((r)[6]),  "=r"((r)[7]), \
          "=r"((r)[8]),  "=r"((r)[9]),  "=r"((r)[10]), "=r"((r)[11]), \
          "=r"((r)[12]), "=r"((r)[13]), "=r"((r)[14]), "=r"((r)[15]), \
          "=r"((r)[16]), "=r"((r)[17]), "=r"((r)[18]), "=r"((r)[19]), \
          "=r"((r)[20]), "=r"((r)[21]), "=r"((r)[22]), "=r"((r)[23]), \
          "=r"((r)[24]), "=r"((r)[25]), "=r"((r)[26]), "=r"((r)[27]), \
          "=r"((r)[28]), "=r"((r)[29]), "=r"((r)[30]), "=r"((r)[31]) \
        : "r"(addr))
#endif  // HAS_TCG

#if !HAS_TCG
// ---------------- mma.sync helpers (generic pass) ----------------------------
#define LDSM4(r0,r1,r2,r3,addr) \
    asm volatile("ldmatrix.sync.aligned.m8n8.x4.shared.b16 {%0,%1,%2,%3}, [%4];" \
                 : "=r"(r0),"=r"(r1),"=r"(r2),"=r"(r3) : "r"(addr))
__device__ __forceinline__ void mma16816(float* c, const uint32_t* a, const uint32_t* b){
    asm volatile("mma.sync.aligned.m16n8k16.row.col.f32.bf16.bf16.f32 "
                 "{%0,%1,%2,%3}, {%4,%5,%6,%7}, {%8,%9}, {%0,%1,%2,%3};"
                 : "+f"(c[0]),"+f"(c[1]),"+f"(c[2]),"+f"(c[3])
                 : "r"(a[0]),"r"(a[1]),"r"(a[2]),"r"(a[3]),"r"(b[0]),"r"(b[1]));
}
#define CPA16(dst, src) asm volatile("cp.async.cg.shared.global [%0], [%1], 16;" :: "r"(dst), "l"(src))
#define CPA_COMMIT() asm volatile("cp.async.commit_group;" ::: "memory")
#define CPA_WAIT0()  asm volatile("cp.async.wait_group 0;" ::: "memory")
#endif

// ---------------------------------------------------------------------------
// 3-pass bf16 (hi/lo split) GEMM:  C[M,Ntot] = A[M,GK] * B^T  (B:[Ntot,GK])
// A,B K-major bf16; C fp32 (+optional bias). M%128==0, Ntot%128==0.
// tcgen05 on arch-specific builds; mma.sync (legacy HMMA) otherwise.
// ---------------------------------------------------------------------------
__global__ __launch_bounds__(256) void gemm_bf16_3p(
    const __nv_bfloat16* __restrict__ Ah, const __nv_bfloat16* __restrict__ Al,
    const __nv_bfloat16* __restrict__ Bh, const __nv_bfloat16* __restrict__ Bl,
    float* __restrict__ C, int Ntot, const float* __restrict__ bias)
{
    extern __shared__ char smem[];
    const uint32_t sbase = smem_u32(smem);
    const int tid = threadIdx.x;
    const int wid = tid >> 5;
    const int lane = tid & 31;
    const int row0 = blockIdx.y * MT;
    const int col0 = blockIdx.x * NT;

    // common per-thread load coordinates: 128 rows x 128B, 2 threads/row
    const int ar = tid >> 1;           // row 0..127
    const int ac = (tid & 1) * 64;     // byte half
    const char* gAh0 = (const char*)Ah + (size_t)(row0 + ar) * (GK*2) + ac;
    const char* gAl0 = (const char*)Al + (size_t)(row0 + ar) * (GK*2) + ac;
    const char* gBh0 = (const char*)Bh + (size_t)(col0 + ar) * (GK*2) + ac;
    const char* gBl0 = (const char*)Bl + (size_t)(col0 + ar) * (GK*2) + ac;

#if HAS_TCG
    // ======================= tcgen05 path ====================================
    if (wid == 0) {
        asm volatile("tcgen05.alloc.cta_group::1.sync.aligned.shared::cta.b32 [%0], %1;"
                     :: "r"(sbase), "r"(128u) : "memory");
    }
    if (tid == 0) { mbar_init(sbase + 8, 1); mbar_init(sbase + 16, 1); }
    __syncthreads();
    uint32_t tmem;
    asm volatile("ld.shared.b32 %0, [%1];" : "=r"(tmem) : "r"(sbase));
    if (wid == 0)
        asm volatile("tcgen05.relinquish_alloc_permit.cta_group::1.sync.aligned;");

    uint32_t leader = 0;
    if (wid == 0) leader = elect1();

    auto load_chunk = [&](int st, int ch) {
        const int kb = ch * 128;
        const uint32_t sa_h = SM_TILE0 + st*STAGE_BYTES;
        const uint32_t sa_l = sa_h + A_BYTES;
        const uint32_t sb_h = sa_h + 2*A_BYTES;
        const uint32_t sb_l = sb_h + B_BYTES;
        #pragma unroll
        for (int j = 0; j < 4; j++) {
            uint32_t o  = ar*128 + ac + j*16;
            uint32_t so = swz(o);
            *(float4*)(smem + sa_h + so) = *(const float4*)(gAh0 + kb + j*16);
            *(float4*)(smem + sa_l + so) = *(const float4*)(gAl0 + kb + j*16);
            *(float4*)(smem + sb_h + so) = *(const float4*)(gBh0 + kb + j*16);
            *(float4*)(smem + sb_l + so) = *(const float4*)(gBl0 + kb + j*16);
        }
    };

    load_chunk(0, 0);
    FENCE_ASYNC();
    __syncthreads();

    int ph0 = 0, ph1 = 0;
    uint32_t first = 0;

    for (int ch = 0; ch < NCH; ch++) {
        const int b = ch & 1;
        if (leader) {
            const uint32_t sa = SM_TILE0 + b*STAGE_BYTES;
            const uint64_t dAh = MK_DESC(sbase + sa);
            const uint64_t dAl = MK_DESC(sbase + sa + A_BYTES);
            const uint64_t dBh = MK_DESC(sbase + sa + 2*A_BYTES);
            const uint64_t dBl = MK_DESC(sbase + sa + 2*A_BYTES + B_BYTES);
            #pragma unroll
            for (int k = 0; k < 4; k++) {
                mma_bf16_ss(tmem, dAh + k*2, dBh + k*2, first); first = 1;
                mma_bf16_ss(tmem, dAh + k*2, dBl + k*2, 1);
                mma_bf16_ss(tmem, dAl + k*2, dBh + k*2, 1);
            }
            tc_commit(sbase + 8 + b*8);
        }
        if (ch + 1 < NCH) {
            const int nb = b ^ 1;
            if (ch >= 1) {
                if (nb == 0) { mbar_wait(sbase + 8, ph0);  ph0 ^= 1; }
                else         { mbar_wait(sbase + 16, ph1); ph1 ^= 1; }
            }
            load_chunk(nb, ch + 1);
            FENCE_ASYNC();
            __syncthreads();
        }
    }

    mbar_wait(sbase + 16, ph1);   // last commit (ch=11, buffer 1)
    TC_FENCE_AFTER();

    if (wid < 4) {
        const int r = row0 + wid*32 + lane;
        float* crow = C + (size_t)r * Ntot;
        #pragma unroll
        for (int chk = 0; chk < 4; chk++) {
            uint32_t regs[32];
            LDTM32(regs, tmem + chk*32);
            TC_WAIT_LD();
            const int c0 = col0 + chk*32;
            #pragma unroll
            for (int j = 0; j < 32; j += 4) {
                float4 v;
                v.x = __uint_as_float(regs[j+0]);
                v.y = __uint_as_float(regs[j+1]);
                v.z = __uint_as_float(regs[j+2]);
                v.w = __uint_as_float(regs[j+3]);
                if (bias) {
                    v.x += bias[c0+j+0]; v.y += bias[c0+j+1];
                    v.z += bias[c0+j+2]; v.w += bias[c0+j+3];
                }
                *(float4*)(crow + c0 + j) = v;
            }
        }
        TC_FENCE_BEFORE();
    }
    __syncthreads();
    if (tid == 0) {
        asm volatile("mbarrier.inval.shared.b64 [%0];" :: "r"(sbase + 8) : "memory");
        asm volatile("mbarrier.inval.shared.b64 [%0];" :: "r"(sbase + 16) : "memory");
    }
    __syncthreads();
    if (wid == 0) {
        asm volatile("tcgen05.dealloc.cta_group::1.sync.aligned.b32 %0, %1;"
                     :: "r"(tmem), "r"(128u));
    }

#else
    // ======================= mma.sync fallback ===============================
    const int wr = wid & 3;     // warp M position (4 x 32)
    const int wc = wid >> 2;    // warp N position (2 x 64)

    auto load_chunk = [&](int st, int ch) {
        const int kb = ch * 128;
        const uint32_t sa_h = sbase + SM_TILE0 + st*STAGE_BYTES;
        const uint32_t sa_l = sa_h + A_BYTES;
        const uint32_t sb_h = sa_h + 2*A_BYTES;
        const uint32_t sb_l = sb_h + B_BYTES;
        #pragma unroll
        for (int j = 0; j < 4; j++) {
            uint32_t so = swz(ar*128 + ac + j*16);
            CPA16(sa_h + so, gAh0 + kb + j*16);
            CPA16(sa_l + so, gAl0 + kb + j*16);
            CPA16(sb_h + so, gBh0 + kb + j*16);
            CPA16(sb_l + so, gBl0 + kb + j*16);
        }
    };

    float acc[2][8][4];
    #pragma unroll
    for (int i = 0; i < 2; i++)
        #pragma unroll
        for (int j = 0; j < 8; j++)
            #pragma unroll
            for (int q = 0; q < 4; q++) acc[i][j][q] = 0.f;

    load_chunk(0, 0);
    CPA_COMMIT();
    CPA_WAIT0();
    __syncthreads();

    // precomputed swizzled fragment offsets (row deltas of 16 rows = +2048
    // commute with the swizzle since it only mixes bits [4:10))
    const uint32_t aoff0 = swz((wr*32 + (lane & 15))*128 + (lane >> 4)*16);
    const uint32_t boff0 = swz((wc*64 + (lane >> 4)*8 + (lane & 7))*128 + ((lane >> 3) & 1)*16);

    for (int ch = 0; ch < NCH; ch++) {
        const int b = ch & 1;
        if (ch + 1 < NCH) { load_chunk(b ^ 1, ch + 1); CPA_COMMIT(); }

        const uint32_t sa_h = sbase + SM_TILE0 + b*STAGE_BYTES;
        const uint32_t sa_l = sa_h + A_BYTES;
        const uint32_t sb_h = sa_h + 2*A_BYTES;
        const uint32_t sb_l = sb_h + B_BYTES;

        #pragma unroll
        for (int ks = 0; ks < 4; ks++) {
            // ks advances 32B along the row: swizzle-compatible? 32B step flips
            // bit 5 -> affected by XOR of bits [7:10). Recompute full swizzle:
            const uint32_t ao = swz((wr*32 + (lane & 15))*128 + ks*32 + (lane >> 4)*16);
            const uint32_t bo = swz((wc*64 + (lane >> 4)*8 + (lane & 7))*128 + ks*32 + ((lane >> 3) & 1)*16);
            (void)aoff0; (void)boff0;

            uint32_t ah[2][4], al[2][4], bh[4][4], bl[4][4];
            #pragma unroll
            for (int mt = 0; mt < 2; mt++) {
                LDSM4(ah[mt][0], ah[mt][1], ah[mt][2], ah[mt][3], sa_h + ao + mt*2048);
                LDSM4(al[mt][0], al[mt][1], al[mt][2], al[mt][3], sa_l + ao + mt*2048);
            }
            #pragma unroll
            for (int t = 0; t < 4; t++) {
                LDSM4(bh[t][0], bh[t][1], bh[t][2], bh[t][3], sb_h + bo + t*2048);
                LDSM4(bl[t][0], bl[t][1], bl[t][2], bl[t][3], sb_l + bo + t*2048);
            }
            #pragma unroll
            for (int mt = 0; mt < 2; mt++)
                #pragma unroll
                for (int t = 0; t < 4; t++) {
                    mma16816(acc[mt][2*t+0], ah[mt], &bh[t][0]);
                    mma16816(acc[mt][2*t+1], ah[mt], &bh[t][2]);
                    mma16816(acc[mt][2*t+0], ah[mt], &bl[t][0]);
                    mma16816(acc[mt][2*t+1], ah[mt], &bl[t][2]);
                    mma16816(acc[mt][2*t+0], al[mt], &bh[t][0]);
                    mma16816(acc[mt][2*t+1], al[mt], &bh[t][2]);
                }
        }
        if (ch + 1 < NCH) CPA_WAIT0();
        __syncthreads();
    }

    // epilogue
    #pragma unroll
    for (int mt = 0; mt < 2; mt++)
        #pragma unroll
        for (int nt = 0; nt < 8; nt++) {
            const int rg = row0 + wr*32 + mt*16 + (lane >> 2);
            const int cg = col0 + wc*64 + nt*8 + (lane & 3)*2;
            float bx = 0.f, by = 0.f;
            if (bias) { bx = bias[cg]; by = bias[cg+1]; }
            float* p = C + (size_t)rg * Ntot + cg;
            float2 v0; v0.x = acc[mt][nt][0] + bx; v0.y = acc[mt][nt][1] + by;
            float2 v1; v1.x = acc[mt][nt][2] + bx; v1.y = acc[mt][nt][3] + by;
            *(float2*)p = v0;
            *(float2*)(p + (size_t)8 * Ntot) = v1;
        }
#endif
}

// ---------------------------------------------------------------------------
// fp32 -> bf16 hi/lo split (elementwise)
// ---------------------------------------------------------------------------
__global__ __launch_bounds__(256) void split_kernel(
    const float* __restrict__ in, __nv_bfloat16* __restrict__ h,
    __nv_bfloat16* __restrict__ l, size_t n4)
{
    size_t i = (size_t)blockIdx.x * blockDim.x + threadIdx.x;
    if (i >= n4) return;
    float4 v = ((const float4*)in)[i];
    __nv_bfloat16 h0 = __float2bfloat16(v.x), h1 = __float2bfloat16(v.y);
    __nv_bfloat16 h2 = __float2bfloat16(v.z), h3 = __float2bfloat16(v.w);
    __nv_bfloat16 l0 = __float2bfloat16(v.x - __bfloat162float(h0));
    __nv_bfloat16 l1 = __float2bfloat16(v.y - __bfloat162float(h1));
    __nv_bfloat16 l2 = __float2bfloat16(v.z - __bfloat162float(h2));
    __nv_bfloat16 l3 = __float2bfloat16(v.w - __bfloat162float(h3));
    ((__nv_bfloat162*)h)[2*i]   = __halves2bfloat162(h0, h1);
    ((__nv_bfloat162*)h)[2*i+1] = __halves2bfloat162(h2, h3);
    ((__nv_bfloat162*)l)[2*i]   = __halves2bfloat162(l0, l1);
    ((__nv_bfloat162*)l)[2*i+1] = __halves2bfloat162(l2, l3);
}

// ---------------------------------------------------------------------------
// W [K,N] fp32 -> transposed bf16 hi/lo [N,K]
// ---------------------------------------------------------------------------
__global__ __launch_bounds__(256) void transpose_split(
    const float* __restrict__ W, __nv_bfloat16* __restrict__ h,
    __nv_bfloat16* __restrict__ l, int K, int N)
{
    __shared__ float t[32][33];
    const int n0 = blockIdx.x * 32, k0 = blockIdx.y * 32;
    const int tx = threadIdx.x & 31, ty = threadIdx.x >> 5;
    #pragma unroll
    for (int i = ty; i < 32; i += 8)
        t[i][tx] = W[(size_t)(k0 + i) * N + n0 + tx];
    __syncthreads();
    #pragma unroll
    for (int i = ty; i < 32; i += 8) {
        float v = t[tx][i];
        __nv_bfloat16 hv = __float2bfloat16(v);
        __nv_bfloat16 lv = __float2bfloat16(v - __bfloat162float(hv));
        h[(size_t)(n0 + i) * K + k0 + tx] = hv;
        l[(size_t)(n0 + i) * K + k0 + tx] = lv;
    }
}

// ---------------------------------------------------------------------------
// fused norms + cross-cov + temperature + softmax (one CTA per (b,h))
// ---------------------------------------------------------------------------
__global__ __launch_bounds__(256) void attn_kernel(const float* __restrict__ temp)
{
    const int bh = blockIdx.x;
    const int b  = bh / Hh, h = bh % Hh;
    const int tid = threadIdx.x;
    const int tx = tid & 15, ty = tid >> 4;

    __shared__ float Qs[64][68];
    __shared__ float Ks[64][68];
    __shared__ float ps[256];
    __shared__ float normQ[64], normK[64];

    const size_t rowbase = (size_t)b * Nn;
    const int qoff = h * dh;
    const int koff = Dd + h * dh;

    float acc[4][4];
    #pragma unroll
    for (int i = 0; i < 4; i++)
        #pragma unroll
        for (int j = 0; j < 4; j++) acc[i][j] = 0.f;
    float pssq = 0.f;

    const int lr = tid >> 4;
    const int lc = (tid & 15) << 2;
    const int scol  = tid & 127;
    const int shalf = (tid >> 7) * 32;

    for (int n0 = 0; n0 < Nn; n0 += 64) {
        #pragma unroll
        for (int pp = 0; pp < 64; pp += 16) {
            const size_t grow = (rowbase + n0 + pp + lr) * QKVC;
            *(float4*)&Qs[pp + lr][lc] = *(const float4*)(g_qkv + grow + qoff + lc);
            *(float4*)&Ks[pp + lr][lc] = *(const float4*)(g_qkv + grow + koff + lc);
        }
        __syncthreads();
        #pragma unroll 4
        for (int n = 0; n < 64; n++) {
            float rq[4], rk[4];
            *(float4*)rq = *(const float4*)&Qs[n][tx * 4];
            *(float4*)rk = *(const float4*)&Ks[n][ty * 4];
            #pragma unroll
            for (int i = 0; i < 4; i++)
                #pragma unroll
                for (int j = 0; j < 4; j++)
                    acc[i][j] = fmaf(rk[i], rq[j], acc[i][j]);
        }
        {
            const float* colp = (scol < 64) ? &Qs[0][scol] : &Ks[0][scol - 64];
            #pragma unroll
            for (int n = 0; n < 32; n++) {
                const float v = colp[(size_t)(shalf + n) * 68];
                pssq = fmaf(v, v, pssq);
            }
        }
        __syncthreads();
    }

    ps[tid] = pssq;
    __syncthreads();
    if (tid < 128) {
        const float s  = ps[tid] + ps[tid + 128];
        const float nv = fmaxf(sqrtf(s), 1e-12f);
        if (tid < 64) normQ[tid] = nv; else normK[tid - 64] = nv;
    }
    __syncthreads();

    const float tv = temp[h];
    #pragma unroll
    for (int i = 0; i < 4; i++)
        #pragma unroll
        for (int j = 0; j < 4; j++)
            Qs[ty * 4 + i][tx * 4 + j] =
                acc[i][j] * tv / (normK[ty * 4 + i] * normQ[tx * 4 + j]);
    __syncthreads();

    if (tid < 64) {
        const int p = tid;
        float m = -1e30f;
        for (int q = 0; q < 64; q++) m = fmaxf(m, Qs[p][q]);
        float s = 0.f;
        for (int q = 0; q < 64; q++) s += expf(Qs[p][q] - m);
        const float inv = 1.f / s;
        float* op = g_attn + (size_t)bh * 4096 + p * 64;
        for (int q = 0; q < 64; q++) op[q] = expf(Qs[p][q] - m) * inv;
    }
}

// ---------------------------------------------------------------------------
// out[b,h,n,q] = sum_p v[n,p] attn[p,q]
// ---------------------------------------------------------------------------
__global__ __launch_bounds__(256) void av_kernel()
{
    const int bh = blockIdx.x;
    const int nt = blockIdx.y;
    const int b  = bh / Hh, h = bh % Hh;
    const int tid = threadIdx.x;
    const int tx = tid & 15, ty = tid >> 4;

    __shared__ float At[64][68];
    __shared__ float Vs[64][68];

    {
        const float* ap = g_attn + (size_t)bh * 4096;
        #pragma unroll
        for (int pp = 0; pp < 4; pp++) {
            const int idx = pp * 1024 + tid * 4;
            *(float4*)&At[idx >> 6][idx & 63] = *(const float4*)(ap + idx);
        }
    }
    const int lr = tid >> 4, lc = (tid & 15) << 2;
    const int voff = 2 * Dd + h * dh;
    const size_t rowbase = (size_t)b * Nn + nt * 64;
    #pragma unroll
    for (int pp = 0; pp < 64; pp += 16)
        *(float4*)&Vs[pp + lr][lc] =
            *(const float4*)(g_qkv + (rowbase + pp + lr) * QKVC + voff + lc);
    __syncthreads();

    float acc[4][4];
    #pragma unroll
    for (int i = 0; i < 4; i++)
        #pragma unroll
        for (int j = 0; j < 4; j++) acc[i][j] = 0.f;

    #pragma unroll 8
    for (int p = 0; p < 64; p++) {
        float ra[4];
        *(float4*)ra = *(const float4*)&At[p][tx * 4];
        float rv[4];
        #pragma unroll
        for (int i = 0; i < 4; i++) rv[i] = Vs[ty * 4 + i][p];
        #pragma unroll
        for (int i = 0; i < 4; i++)
            #pragma unroll
            for (int j = 0; j < 4; j++)
                acc[i][j] = fmaf(rv[i], ra[j], acc[i][j]);
    }

    #pragma unroll
    for (int i = 0; i < 4; i++) {
        const size_t r = rowbase + ty * 4 + i;
        float4 v;
        v.x = acc[i][0]; v.y = acc[i][1]; v.z = acc[i][2]; v.w = acc[i][3];
        *(float4*)(g_oattn + r * Dd + h * dh + tx * 4) = v;
    }
}

// ---------------------------------------------------------------------------
extern "C" void kernel_launch(void* const* d_in, const int* in_sizes, int n_in,
                              void* d_out, int out_size)
{
    const float* x     = (const float*)d_in[0];
    const float* Wqkv  = (const float*)d_in[1];
    const float* temp  = (const float*)d_in[2];
    const float* Wout  = (const float*)d_in[3];
    const float* bout  = (const float*)d_in[4];
    float* out = (float*)d_out;

    float *qkv, *oattn;
    __nv_bfloat16 *xh, *xl, *wh, *wl, *woh, *wol, *oh, *ol;
    cudaGetSymbolAddress((void**)&qkv,   g_qkv);
    cudaGetSymbolAddress((void**)&oattn, g_oattn);
    cudaGetSymbolAddress((void**)&xh,  g_xh);  cudaGetSymbolAddress((void**)&xl,  g_xl);
    cudaGetSymbolAddress((void**)&wh,  g_wh);  cudaGetSymbolAddress((void**)&wl,  g_wl);
    cudaGetSymbolAddress((void**)&woh, g_woh); cudaGetSymbolAddress((void**)&wol, g_wol);
    cudaGetSymbolAddress((void**)&oh,  g_oh);  cudaGetSymbolAddress((void**)&ol,  g_ol);

    cudaFuncSetAttribute(gemm_bf16_3p, cudaFuncAttributeMaxDynamicSharedMemorySize, GEMM_SMEM);

    // 1) split inputs to bf16 hi/lo
    {
        size_t n4 = (size_t)Mrows * Dd / 4;
        split_kernel<<<(unsigned)((n4 + 255) / 256), 256>>>(x, xh, xl, n4);
    }
    transpose_split<<<dim3(QKVC/32, Dd/32), 256>>>(Wqkv, wh, wl, Dd, QKVC);
    transpose_split<<<dim3(Dd/32,  Dd/32), 256>>>(Wout, woh, wol, Dd, Dd);

    // 2) qkv = x @ Wqkv  (tensor cores, 3-pass bf16)
    gemm_bf16_3p<<<dim3(QKVC/NT, Mrows/MT), 256, GEMM_SMEM>>>(xh, xl, wh, wl, qkv, QKVC, nullptr);

    // 3) fused normalize + cross-covariance + temperature + softmax
    attn_kernel<<<dim3(Bc * Hh), 256>>>(temp);

    // 4) out = v @ attn
    av_kernel<<<dim3(Bc * Hh, Nn / 64), 256>>>();

    // 5) split oattn, final projection + bias (tensor cores)
    {
        size_t n4 = (size_t)Mrows * Dd / 4;
        split_kernel<<<(unsigned)((n4 + 255) / 256), 256>>>(oattn, oh, ol, n4);
    }
    gemm_bf16_3p<<<dim3(Dd/NT, Mrows/MT), 256, GEMM_SMEM>>>(oh, ol, woh, wol, out, Dd, bout);
}

// round 4
// speedup vs baseline: 2.5605x; 1.1142x over previous
#include <cuda_runtime.h>
#include <cuda_bf16.h>
#include <math.h>
#include <stdint.h>

#define Bc 8
#define Nn 4096
#define Dd 768
#define Hh 12
#define dh 64
#define Mrows (Bc*Nn)      /* 32768 */
#define QKVC  (3*Dd)       /* 2304  */
#define GK    Dd           /* GEMM K = 768 */

// ---------------- scratch (device globals; allocation-free rule) -----------
__device__ float g_qkv[(size_t)Mrows * QKVC];          // 302 MB
__device__ float g_attn[Bc*Hh*dh*dh];                  // 1.5 MB
__device__ __nv_bfloat16 g_xh[(size_t)Mrows*Dd],  g_xl[(size_t)Mrows*Dd];
__device__ __nv_bfloat16 g_wh[(size_t)QKVC*Dd],   g_wl[(size_t)QKVC*Dd];   // [N,K]
__device__ __nv_bfloat16 g_woh[(size_t)Dd*Dd],    g_wol[(size_t)Dd*Dd];
__device__ __nv_bfloat16 g_oh[(size_t)Mrows*Dd],  g_ol[(size_t)Mrows*Dd];

// ---------------- arch feature gate -----------------------------------------
#if defined(__CUDA_ARCH_FEAT_SM103_ALL) || defined(__CUDA_ARCH_FEAT_SM100_ALL) || defined(__CUDA_ARCH_FEAT_SM101_ALL)
#define HAS_TCG 1
#else
#define HAS_TCG 0
#endif

// ---------------- common helpers --------------------------------------------
__device__ __forceinline__ uint32_t smem_u32(const void* p){
    uint32_t a;
    asm("{ .reg .u64 t; cvta.to.shared.u64 t, %1; cvt.u32.u64 %0, t; }" : "=r"(a) : "l"(p));
    return a;
}
__device__ __forceinline__ uint32_t swz(uint32_t o){ return o ^ ((o >> 3) & 0x70); }

#define CPA16(dst, src) asm volatile("cp.async.cg.shared.global [%0], [%1], 16;" :: "r"(dst), "l"(src))
#define CPA_COMMIT() asm volatile("cp.async.commit_group;" ::: "memory")
#define CPA_WAIT0()  asm volatile("cp.async.wait_group 0;" ::: "memory")

// ---------------- GEMM tile geometry ----------------------------------------
#define MT 128
#define NT 256
#define KCH 64
#define NCH (GK/KCH)            /* 12 */
#define A_BYTES (MT*128)        /* 16384 */
#define B_BYTES (NT*128)        /* 32768 */
#define STAGE_BYTES (2*A_BYTES + 2*B_BYTES)  /* 98304 */
#define SM_TILE0 1024
#define GEMM_SMEM (SM_TILE0 + 2*STAGE_BYTES) /* 197632 */

#if HAS_TCG
// ---------------- tcgen05 helpers (arch-specific pass only) -----------------
__device__ __forceinline__ uint32_t elect1(){
    uint32_t p;
    asm volatile("{\n\t.reg .pred p;\n\telect.sync _|p, 0xFFFFFFFF;\n\tselp.b32 %0, 1, 0, p;\n\t}" : "=r"(p));
    return p;
}
static constexpr uint64_t DESC_BASE_SW128 =
    (uint64_t(2) << 61) | (uint64_t(1) << 46) | (uint64_t(64) << 32) | (uint64_t(1) << 16);
#define MK_DESC(a) (DESC_BASE_SW128 | ((uint64_t)((a) >> 4) & 0x3FFF))
// idesc: F32 accum, BF16 a/b, M=128, N=256
#define GEMM_IDESC 0x8400490u

__device__ __forceinline__ void mma_bf16_ss(uint32_t d, uint64_t a, uint64_t b, uint32_t en){
    asm volatile(
        "{\n\t.reg .pred p;\n\tsetp.ne.u32 p, %3, 0;\n\t"
        "tcgen05.mma.cta_group::1.kind::f16 [%0], %1, %2, %4, {%5,%5,%5,%5}, p;\n\t}"
        :: "r"(d), "l"(a), "l"(b), "r"(en), "r"(GEMM_IDESC), "r"(0u) : "memory");
}
__device__ __forceinline__ void tc_commit(uint32_t mbar){
    asm volatile("tcgen05.commit.cta_group::1.mbarrier::arrive::one.shared::cluster.b64 [%0];"
                 :: "r"(mbar) : "memory");
}
__device__ __forceinline__ void mbar_init(uint32_t mbar, uint32_t cnt){
    asm volatile("mbarrier.init.shared.b64 [%0], %1;" :: "r"(mbar), "r"(cnt) : "memory");
}
__device__ __forceinline__ void mbar_wait(uint32_t mbar, uint32_t parity){
    asm volatile(
        "{\n\t.reg .pred P;\n\tWL_%=:\n\t"
        "mbarrier.try_wait.parity.acquire.cta.shared::cta.b64 P, [%0], %1, 0x989680;\n\t"
        "@P bra.uni WD_%=;\n\tbra.uni WL_%=;\n\tWD_%=:\n\t}"
        :: "r"(mbar), "r"(parity) : "memory");
}
#define FENCE_ASYNC()  asm volatile("fence.proxy.async.shared::cta;" ::: "memory")
#define TC_FENCE_AFTER()  asm volatile("tcgen05.fence::after_thread_sync;" ::: "memory")
#define TC_FENCE_BEFORE() asm volatile("tcgen05.fence::before_thread_sync;" ::: "memory")
#define TC_WAIT_LD() asm volatile("tcgen05.wait::ld.sync.aligned;" ::: "memory")

#define LDTM32(r, addr) \
    asm volatile( \
        "tcgen05.ld.sync.aligned.32x32b.x32.b32 " \
        "{%0, %1, %2, %3, %4, %5, %6, %7, " \
        " %8, %9, %10, %11, %12, %13, %14, %15, " \
        " %16, %17, %18, %19, %20, %21, %22, %23, " \
        " %24, %25, %26, %27, %28, %29, %30, %31}, [%32];" \
        : "=r"((r)[0]),  "=r"((r)[1]),  "=r"((r)[2]),  "=r"((r)[3]), \
          "=r"((r)[4]),  "=r"((r)[5]),  "=r"((r)[6]),  "=r"((r)[7]), \
          "=r"((r)[8]),  "=r"((r)[9]),  "=r"((r)[10]), "=r"((r)[11]), \
          "=r"((r)[12]), "=r"((r)[13]), "=r"((r)[14]), "=r"((r)[15]), \
          "=r"((r)[16]), "=r"((r)[17]), "=r"((r)[18]), "=r"((r)[19]), \
          "=r"((r)[20]), "=r"((r)[21]), "=r"((r)[22]), "=r"((r)[23]), \
          "=r"((r)[24]), "=r"((r)[25]), "=r"((r)[26]), "=r"((r)[27]), \
          "=r"((r)[28]), "=r"((r)[29]), "=r"((r)[30]), "=r"((r)[31]) \
        : "r"(addr))
#endif  // HAS_TCG

#if !HAS_TCG
// ---------------- mma.sync helpers (generic pass) ----------------------------
#define LDSM4(r0,r1,r2,r3,addr) \
    asm volatile("ldmatrix.sync.aligned.m8n8.x4.shared.b16 {%0,%1,%2,%3}, [%4];" \
                 : "=r"(r0),"=r"(r1),"=r"(r2),"=r"(r3) : "r"(addr))
__device__ __forceinline__ void mma16816(float* c, const uint32_t* a, const uint32_t* b){
    asm volatile("mma.sync.aligned.m16n8k16.row.col.f32.bf16.bf16.f32 "
                 "{%0,%1,%2,%3}, {%4,%5,%6,%7}, {%8,%9}, {%0,%1,%2,%3};"
                 : "+f"(c[0]),"+f"(c[1]),"+f"(c[2]),"+f"(c[3])
                 : "r"(a[0]),"r"(a[1]),"r"(a[2]),"r"(a[3]),"r"(b[0]),"r"(b[1]));
}
#endif

// ---------------------------------------------------------------------------
// 3-pass bf16 (hi/lo split) GEMM:  C[M,Ntot] = A[M,GK] * B^T  (B:[Ntot,GK])
// A,B K-major bf16; C fp32 (+optional bias). M%128==0, Ntot%256==0.
// tcgen05 on arch-specific builds; mma.sync (legacy HMMA) otherwise.
// ---------------------------------------------------------------------------
__global__ __launch_bounds__(256) void gemm_bf16_3p(
    const __nv_bfloat16* __restrict__ Ah, const __nv_bfloat16* __restrict__ Al,
    const __nv_bfloat16* __restrict__ Bh, const __nv_bfloat16* __restrict__ Bl,
    float* __restrict__ C, int Ntot, const float* __restrict__ bias)
{
    extern __shared__ char smem[];
    const uint32_t sbase = smem_u32(smem);
    const int tid = threadIdx.x;
    const int wid = tid >> 5;
    const int lane = tid & 31;
    const int row0 = blockIdx.y * MT;
    const int col0 = blockIdx.x * NT;

    // A: 2 threads/row (4x16B each). B: 1 thread/row (8x16B each).
    const int ar = tid >> 1;
    const int ac = (tid & 1) * 64;
    const int br = tid;
    const char* gAh0 = (const char*)Ah + (size_t)(row0 + ar) * (GK*2) + ac;
    const char* gAl0 = (const char*)Al + (size_t)(row0 + ar) * (GK*2) + ac;
    const char* gBh0 = (const char*)Bh + (size_t)(col0 + br) * (GK*2);
    const char* gBl0 = (const char*)Bl + (size_t)(col0 + br) * (GK*2);

    // cp.async-based tile loader (shared by both paths)
    auto load_chunk = [&](int st, int ch) {
        const int kb = ch * 128;
        const uint32_t sa_h = sbase + SM_TILE0 + st*STAGE_BYTES;
        const uint32_t sa_l = sa_h + A_BYTES;
        const uint32_t sb_h = sa_h + 2*A_BYTES;
        const uint32_t sb_l = sb_h + B_BYTES;
        #pragma unroll
        for (int j = 0; j < 4; j++) {
            uint32_t so = swz(ar*128 + ac + j*16);
            CPA16(sa_h + so, gAh0 + kb + j*16);
            CPA16(sa_l + so, gAl0 + kb + j*16);
        }
        #pragma unroll
        for (int j = 0; j < 8; j++) {
            uint32_t so = swz(br*128 + j*16);
            CPA16(sb_h + so, gBh0 + kb + j*16);
            CPA16(sb_l + so, gBl0 + kb + j*16);
        }
    };

#if HAS_TCG
    // ======================= tcgen05 path ====================================
    if (wid == 0) {
        asm volatile("tcgen05.alloc.cta_group::1.sync.aligned.shared::cta.b32 [%0], %1;"
                     :: "r"(sbase), "r"(256u) : "memory");
    }
    if (tid == 0) { mbar_init(sbase + 8, 1); mbar_init(sbase + 16, 1); }
    __syncthreads();
    uint32_t tmem;
    asm volatile("ld.shared.b32 %0, [%1];" : "=r"(tmem) : "r"(sbase));
    if (wid == 0)
        asm volatile("tcgen05.relinquish_alloc_permit.cta_group::1.sync.aligned;");

    uint32_t leader = 0;
    if (wid == 0) leader = elect1();

    load_chunk(0, 0);
    CPA_COMMIT();
    CPA_WAIT0();
    __syncthreads();
    FENCE_ASYNC();

    int ph0 = 0, ph1 = 0;
    uint32_t first = 0;

    for (int ch = 0; ch < NCH; ch++) {
        const int b = ch & 1;
        if (leader) {
            const uint32_t sa = sbase + SM_TILE0 + b*STAGE_BYTES;
            const uint64_t dAh = MK_DESC(sa);
            const uint64_t dAl = MK_DESC(sa + A_BYTES);
            const uint64_t dBh = MK_DESC(sa + 2*A_BYTES);
            const uint64_t dBl = MK_DESC(sa + 2*A_BYTES + B_BYTES);
            #pragma unroll
            for (int k = 0; k < 4; k++) {
                mma_bf16_ss(tmem, dAh + k*2, dBh + k*2, first); first = 1;
                mma_bf16_ss(tmem, dAh + k*2, dBl + k*2, 1);
                mma_bf16_ss(tmem, dAl + k*2, dBh + k*2, 1);
            }
            tc_commit(sbase + 8 + b*8);
        }
        if (ch + 1 < NCH) {
            const int nb = b ^ 1;
            if (ch >= 1) {   // MMAs of chunk ch-1 (buffer nb) must be done
                if (nb == 0) { mbar_wait(sbase + 8, ph0);  ph0 ^= 1; }
                else         { mbar_wait(sbase + 16, ph1); ph1 ^= 1; }
            }
            load_chunk(nb, ch + 1);
            CPA_COMMIT();
            CPA_WAIT0();
            __syncthreads();
            FENCE_ASYNC();
        }
    }

    mbar_wait(sbase + 16, ph1);   // last commit (ch=11, buffer 1)
    TC_FENCE_AFTER();

    if (wid < 4) {
        const int r = row0 + wid*32 + lane;
        float* crow = C + (size_t)r * Ntot;
        #pragma unroll
        for (int chk = 0; chk < 8; chk++) {
            uint32_t regs[32];
            LDTM32(regs, tmem + chk*32);
            TC_WAIT_LD();
            const int c0 = col0 + chk*32;
            #pragma unroll
            for (int j = 0; j < 32; j += 4) {
                float4 v;
                v.x = __uint_as_float(regs[j+0]);
                v.y = __uint_as_float(regs[j+1]);
                v.z = __uint_as_float(regs[j+2]);
                v.w = __uint_as_float(regs[j+3]);
                if (bias) {
                    v.x += bias[c0+j+0]; v.y += bias[c0+j+1];
                    v.z += bias[c0+j+2]; v.w += bias[c0+j+3];
                }
                *(float4*)(crow + c0 + j) = v;
            }
        }
        TC_FENCE_BEFORE();
    }
    __syncthreads();
    if (tid == 0) {
        asm volatile("mbarrier.inval.shared.b64 [%0];" :: "r"(sbase + 8) : "memory");
        asm volatile("mbarrier.inval.shared.b64 [%0];" :: "r"(sbase + 16) : "memory");
    }
    __syncthreads();
    if (wid == 0) {
        asm volatile("tcgen05.dealloc.cta_group::1.sync.aligned.b32 %0, %1;"
                     :: "r"(tmem), "r"(256u));
    }

#else
    // ======================= mma.sync fallback ===============================
    const int wr = wid & 3;     // warp M position (4 x 32 rows)
    const int wc = wid >> 2;    // warp N position (2 x 128 cols)

    float acc[2][2][8][4];
    #pragma unroll
    for (int mt = 0; mt < 2; mt++)
        #pragma unroll
        for (int ns = 0; ns < 2; ns++)
            #pragma unroll
            for (int j = 0; j < 8; j++)
                #pragma unroll
                for (int q = 0; q < 4; q++) acc[mt][ns][j][q] = 0.f;

    load_chunk(0, 0);
    CPA_COMMIT();
    CPA_WAIT0();
    __syncthreads();

    for (int ch = 0; ch < NCH; ch++) {
        const int b = ch & 1;
        if (ch + 1 < NCH) { load_chunk(b ^ 1, ch + 1); CPA_COMMIT(); }

        const uint32_t sa_h = sbase + SM_TILE0 + b*STAGE_BYTES;
        const uint32_t sa_l = sa_h + A_BYTES;
        const uint32_t sb_h = sa_h + 2*A_BYTES;
        const uint32_t sb_l = sb_h + B_BYTES;

        #pragma unroll
        for (int ks = 0; ks < 4; ks++) {
            const uint32_t ao = swz((wr*32 + (lane & 15))*128 + ks*32 + (lane >> 4)*16);
            uint32_t ah[2][4], al[2][4];
            #pragma unroll
            for (int mt = 0; mt < 2; mt++) {
                LDSM4(ah[mt][0], ah[mt][1], ah[mt][2], ah[mt][3], sa_h + ao + mt*2048);
                LDSM4(al[mt][0], al[mt][1], al[mt][2], al[mt][3], sa_l + ao + mt*2048);
            }
            #pragma unroll
            for (int ns = 0; ns < 2; ns++) {
                const uint32_t bo = swz((wc*128 + ns*64 + (lane >> 4)*8 + (lane & 7))*128
                                        + ks*32 + ((lane >> 3) & 1)*16);
                uint32_t bh[4][4], bl[4][4];
                #pragma unroll
                for (int t = 0; t < 4; t++) {
                    LDSM4(bh[t][0], bh[t][1], bh[t][2], bh[t][3], sb_h + bo + t*2048);
                    LDSM4(bl[t][0], bl[t][1], bl[t][2], bl[t][3], sb_l + bo + t*2048);
                }
                #pragma unroll
                for (int mt = 0; mt < 2; mt++)
                    #pragma unroll
                    for (int t = 0; t < 4; t++) {
                        mma16816(acc[mt][ns][2*t+0], ah[mt], &bh[t][0]);
                        mma16816(acc[mt][ns][2*t+1], ah[mt], &bh[t][2]);
                        mma16816(acc[mt][ns][2*t+0], ah[mt], &bl[t][0]);
                        mma16816(acc[mt][ns][2*t+1], ah[mt], &bl[t][2]);
                        mma16816(acc[mt][ns][2*t+0], al[mt], &bh[t][0]);
                        mma16816(acc[mt][ns][2*t+1], al[mt], &bh[t][2]);
                    }
            }
        }
        if (ch + 1 < NCH) CPA_WAIT0();
        __syncthreads();
    }

    #pragma unroll
    for (int mt = 0; mt < 2; mt++)
        #pragma unroll
        for (int ns = 0; ns < 2; ns++)
            #pragma unroll
            for (int nt = 0; nt < 8; nt++) {
                const int rg = row0 + wr*32 + mt*16 + (lane >> 2);
                const int cg = col0 + wc*128 + ns*64 + nt*8 + (lane & 3)*2;
                float bx = 0.f, by = 0.f;
                if (bias) { bx = bias[cg]; by = bias[cg+1]; }
                float* p = C + (size_t)rg * Ntot + cg;
                float2 v0; v0.x = acc[mt][ns][nt][0] + bx; v0.y = acc[mt][ns][nt][1] + by;
                float2 v1; v1.x = acc[mt][ns][nt][2] + bx; v1.y = acc[mt][ns][nt][3] + by;
                *(float2*)p = v0;
                *(float2*)(p + (size_t)8 * Ntot) = v1;
            }
#endif
}

// ---------------------------------------------------------------------------
// fp32 -> bf16 hi/lo split (elementwise)
// ---------------------------------------------------------------------------
__global__ __launch_bounds__(256) void split_kernel(
    const float* __restrict__ in, __nv_bfloat16* __restrict__ h,
    __nv_bfloat16* __restrict__ l, size_t n4)
{
    size_t i = (size_t)blockIdx.x * blockDim.x + threadIdx.x;
    if (i >= n4) return;
    float4 v = ((const float4*)in)[i];
    __nv_bfloat16 h0 = __float2bfloat16(v.x), h1 = __float2bfloat16(v.y);
    __nv_bfloat16 h2 = __float2bfloat16(v.z), h3 = __float2bfloat16(v.w);
    __nv_bfloat16 l0 = __float2bfloat16(v.x - __bfloat162float(h0));
    __nv_bfloat16 l1 = __float2bfloat16(v.y - __bfloat162float(h1));
    __nv_bfloat16 l2 = __float2bfloat16(v.z - __bfloat162float(h2));
    __nv_bfloat16 l3 = __float2bfloat16(v.w - __bfloat162float(h3));
    ((__nv_bfloat162*)h)[2*i]   = __halves2bfloat162(h0, h1);
    ((__nv_bfloat162*)h)[2*i+1] = __halves2bfloat162(h2, h3);
    ((__nv_bfloat162*)l)[2*i]   = __halves2bfloat162(l0, l1);
    ((__nv_bfloat162*)l)[2*i+1] = __halves2bfloat162(l2, l3);
}

// ---------------------------------------------------------------------------
// W [K,N] fp32 -> transposed bf16 hi/lo [N,K]
// ---------------------------------------------------------------------------
__global__ __launch_bounds__(256) void transpose_split(
    const float* __restrict__ W, __nv_bfloat16* __restrict__ h,
    __nv_bfloat16* __restrict__ l, int K, int N)
{
    __shared__ float t[32][33];
    const int n0 = blockIdx.x * 32, k0 = blockIdx.y * 32;
    const int tx = threadIdx.x & 31, ty = threadIdx.x >> 5;
    #pragma unroll
    for (int i = ty; i < 32; i += 8)
        t[i][tx] = W[(size_t)(k0 + i) * N + n0 + tx];
    __syncthreads();
    #pragma unroll
    for (int i = ty; i < 32; i += 8) {
        float v = t[tx][i];
        __nv_bfloat16 hv = __float2bfloat16(v);
        __nv_bfloat16 lv = __float2bfloat16(v - __bfloat162float(hv));
        h[(size_t)(n0 + i) * K + k0 + tx] = hv;
        l[(size_t)(n0 + i) * K + k0 + tx] = lv;
    }
}

// ---------------------------------------------------------------------------
// fused norms + cross-cov + temperature + softmax (one CTA per (b,h))
// ---------------------------------------------------------------------------
__global__ __launch_bounds__(256) void attn_kernel(const float* __restrict__ temp)
{
    const int bh = blockIdx.x;
    const int b  = bh / Hh, h = bh % Hh;
    const int tid = threadIdx.x;
    const int tx = tid & 15, ty = tid >> 4;

    __shared__ float Qs[64][68];
    __shared__ float Ks[64][68];
    __shared__ float ps[256];
    __shared__ float normQ[64], normK[64];

    const size_t rowbase = (size_t)b * Nn;
    const int qoff = h * dh;
    const int koff = Dd + h * dh;

    float acc[4][4];
    #pragma unroll
    for (int i = 0; i < 4; i++)
        #pragma unroll
        for (int j = 0; j < 4; j++) acc[i][j] = 0.f;
    float pssq = 0.f;

    const int lr = tid >> 4;
    const int lc = (tid & 15) << 2;
    const int scol  = tid & 127;
    const int shalf = (tid >> 7) * 32;

    for (int n0 = 0; n0 < Nn; n0 += 64) {
        #pragma unroll
        for (int pp = 0; pp < 64; pp += 16) {
            const size_t grow = (rowbase + n0 + pp + lr) * QKVC;
            *(float4*)&Qs[pp + lr][lc] = *(const float4*)(g_qkv + grow + qoff + lc);
            *(float4*)&Ks[pp + lr][lc] = *(const float4*)(g_qkv + grow + koff + lc);
        }
        __syncthreads();
        #pragma unroll 4
        for (int n = 0; n < 64; n++) {
            float rq[4], rk[4];
            *(float4*)rq = *(const float4*)&Qs[n][tx * 4];
            *(float4*)rk = *(const float4*)&Ks[n][ty * 4];
            #pragma unroll
            for (int i = 0; i < 4; i++)
                #pragma unroll
                for (int j = 0; j < 4; j++)
                    acc[i][j] = fmaf(rk[i], rq[j], acc[i][j]);
        }
        {
            const float* colp = (scol < 64) ? &Qs[0][scol] : &Ks[0][scol - 64];
            #pragma unroll
            for (int n = 0; n < 32; n++) {
                const float v = colp[(size_t)(shalf + n) * 68];
                pssq = fmaf(v, v, pssq);
            }
        }
        __syncthreads();
    }

    ps[tid] = pssq;
    __syncthreads();
    if (tid < 128) {
        const float s  = ps[tid] + ps[tid + 128];
        const float nv = fmaxf(sqrtf(s), 1e-12f);
        if (tid < 64) normQ[tid] = nv; else normK[tid - 64] = nv;
    }
    __syncthreads();

    const float tv = temp[h];
    #pragma unroll
    for (int i = 0; i < 4; i++)
        #pragma unroll
        for (int j = 0; j < 4; j++)
            Qs[ty * 4 + i][tx * 4 + j] =
                acc[i][j] * tv / (normK[ty * 4 + i] * normQ[tx * 4 + j]);
    __syncthreads();

    if (tid < 64) {
        const int p = tid;
        float m = -1e30f;
        for (int q = 0; q < 64; q++) m = fmaxf(m, Qs[p][q]);
        float s = 0.f;
        for (int q = 0; q < 64; q++) s += expf(Qs[p][q] - m);
        const float inv = 1.f / s;
        float* op = g_attn + (size_t)bh * 4096 + p * 64;
        for (int q = 0; q < 64; q++) op[q] = expf(Qs[p][q] - m) * inv;
    }
}

// ---------------------------------------------------------------------------
// out[b,h,n,q] = sum_p v[n,p] attn[p,q]  -> written directly as bf16 hi/lo
// into g_oh/g_ol [(b*N+n), (h*64+q)] (the GEMM2 A operand). Fuses the split.
// ---------------------------------------------------------------------------
__global__ __launch_bounds__(256) void av_kernel()
{
    const int bh = blockIdx.x;
    const int nt = blockIdx.y;
    const int b  = bh / Hh, h = bh % Hh;
    const int tid = threadIdx.x;
    const int tx = tid & 15, ty = tid >> 4;

    __shared__ float At[64][68];
    __shared__ float Vs[64][68];

    {
        const float* ap = g_attn + (size_t)bh * 4096;
        #pragma unroll
        for (int pp = 0; pp < 4; pp++) {
            const int idx = pp * 1024 + tid * 4;
            *(float4*)&At[idx >> 6][idx & 63] = *(const float4*)(ap + idx);
        }
    }
    const int lr = tid >> 4, lc = (tid & 15) << 2;
    const int voff = 2 * Dd + h * dh;
    const size_t rowbase = (size_t)b * Nn + nt * 64;
    #pragma unroll
    for (int pp = 0; pp < 64; pp += 16)
        *(float4*)&Vs[pp + lr][lc] =
            *(const float4*)(g_qkv + (rowbase + pp + lr) * QKVC + voff + lc);
    __syncthreads();

    float acc[4][4];
    #pragma unroll
    for (int i = 0; i < 4; i++)
        #pragma unroll
        for (int j = 0; j < 4; j++) acc[i][j] = 0.f;

    #pragma unroll 8
    for (int p = 0; p < 64; p++) {
        float ra[4];
        *(float4*)ra = *(const float4*)&At[p][tx * 4];
        float rv[4];
        #pragma unroll
        for (int i = 0; i < 4; i++) rv[i] = Vs[ty * 4 + i][p];
        #pragma unroll
        for (int i = 0; i < 4; i++)
            #pragma unroll
            for (int j = 0; j < 4; j++)
                acc[i][j] = fmaf(rv[i], ra[j], acc[i][j]);
    }

    #pragma unroll
    for (int i = 0; i < 4; i++) {
        const size_t r = rowbase + ty * 4 + i;
        const size_t off = r * Dd + h * dh + tx * 4;
        __nv_bfloat16 hv[4], lv[4];
        #pragma unroll
        for (int j = 0; j < 4; j++) {
            hv[j] = __float2bfloat16(acc[i][j]);
            lv[j] = __float2bfloat16(acc[i][j] - __bfloat162float(hv[j]));
        }
        *(__nv_bfloat162*)(g_oh + off)     = __halves2bfloat162(hv[0], hv[1]);
        *(__nv_bfloat162*)(g_oh + off + 2) = __halves2bfloat162(hv[2], hv[3]);
        *(__nv_bfloat162*)(g_ol + off)     = __halves2bfloat162(lv[0], lv[1]);
        *(__nv_bfloat162*)(g_ol + off + 2) = __halves2bfloat162(lv[2], lv[3]);
    }
}

// ---------------------------------------------------------------------------
extern "C" void kernel_launch(void* const* d_in, const int* in_sizes, int n_in,
                              void* d_out, int out_size)
{
    const float* x     = (const float*)d_in[0];
    const float* Wqkv  = (const float*)d_in[1];
    const float* temp  = (const float*)d_in[2];
    const float* Wout  = (const float*)d_in[3];
    const float* bout  = (const float*)d_in[4];
    float* out = (float*)d_out;

    float *qkv;
    __nv_bfloat16 *xh, *xl, *wh, *wl, *woh, *wol, *oh, *ol;
    cudaGetSymbolAddress((void**)&qkv,   g_qkv);
    cudaGetSymbolAddress((void**)&xh,  g_xh);  cudaGetSymbolAddress((void**)&xl,  g_xl);
    cudaGetSymbolAddress((void**)&wh,  g_wh);  cudaGetSymbolAddress((void**)&wl,  g_wl);
    cudaGetSymbolAddress((void**)&woh, g_woh); cudaGetSymbolAddress((void**)&wol, g_wol);
    cudaGetSymbolAddress((void**)&oh,  g_oh);  cudaGetSymbolAddress((void**)&ol,  g_ol);

    cudaFuncSetAttribute(gemm_bf16_3p, cudaFuncAttributeMaxDynamicSharedMemorySize, GEMM_SMEM);

    // 1) split inputs to bf16 hi/lo
    {
        size_t n4 = (size_t)Mrows * Dd / 4;
        split_kernel<<<(unsigned)((n4 + 255) / 256), 256>>>(x, xh, xl, n4);
    }
    transpose_split<<<dim3(QKVC/32, Dd/32), 256>>>(Wqkv, wh, wl, Dd, QKVC);
    transpose_split<<<dim3(Dd/32,  Dd/32), 256>>>(Wout, woh, wol, Dd, Dd);

    // 2) qkv = x @ Wqkv  (tcgen05, 3-pass bf16, cp.async pipeline)
    gemm_bf16_3p<<<dim3(QKVC/NT, Mrows/MT), 256, GEMM_SMEM>>>(xh, xl, wh, wl, qkv, QKVC, nullptr);

    // 3) fused normalize + cross-covariance + temperature + softmax
    attn_kernel<<<dim3(Bc * Hh), 256>>>(temp);

    // 4) out = v @ attn  (writes bf16 hi/lo directly — split fused)
    av_kernel<<<dim3(Bc * Hh, Nn / 64), 256>>>();

    // 5) final projection + bias (tcgen05)
    gemm_bf16_3p<<<dim3(Dd/NT, Mrows/MT), 256, GEMM_SMEM>>>(oh, ol, woh, wol, out, Dd, bout);
}

// round 5
// speedup vs baseline: 3.4396x; 1.3433x over previous
#include <cuda_runtime.h>
#include <cuda_bf16.h>
#include <math.h>
#include <stdint.h>

#define Bc 8
#define Nn 4096
#define Dd 768
#define Hh 12
#define dh 64
#define Mrows (Bc*Nn)      /* 32768 */
#define QKVC  (3*Dd)       /* 2304  */
#define GK    Dd           /* GEMM K = 768 */

// ---------------- scratch (device globals; allocation-free rule) -----------
__device__ float g_qkv[(size_t)Mrows * QKVC];          // 302 MB
__device__ float g_attn[Bc*Hh*dh*dh];                  // 1.5 MB
__device__ __nv_bfloat16 g_xh[(size_t)Mrows*Dd],  g_xl[(size_t)Mrows*Dd];
__device__ __nv_bfloat16 g_wh[(size_t)QKVC*Dd],   g_wl[(size_t)QKVC*Dd];   // [N,K]
__device__ __nv_bfloat16 g_woh[(size_t)Dd*Dd],    g_wol[(size_t)Dd*Dd];
__device__ __nv_bfloat16 g_oh[(size_t)Mrows*Dd],  g_ol[(size_t)Mrows*Dd];

// ---------------- arch feature gate -----------------------------------------
#if defined(__CUDA_ARCH_FEAT_SM103_ALL) || defined(__CUDA_ARCH_FEAT_SM100_ALL) || defined(__CUDA_ARCH_FEAT_SM101_ALL)
#define HAS_TCG 1
#else
#define HAS_TCG 0
#endif

// ---------------- common helpers --------------------------------------------
__device__ __forceinline__ uint32_t smem_u32(const void* p){
    uint32_t a;
    asm("{ .reg .u64 t; cvta.to.shared.u64 t, %1; cvt.u32.u64 %0, t; }" : "=r"(a) : "l"(p));
    return a;
}
__device__ __forceinline__ uint32_t swz64(uint32_t o){ return o ^ ((o >> 3) & 0x30); }

#define CPA16(dst, src) asm volatile("cp.async.cg.shared.global [%0], [%1], 16;" :: "r"(dst), "l"(src))
#define CPA_COMMIT() asm volatile("cp.async.commit_group;" ::: "memory")
#define CPA_WAIT1()  asm volatile("cp.async.wait_group 1;" ::: "memory")
#define CPA_WAIT0()  asm volatile("cp.async.wait_group 0;" ::: "memory")

// ---------------- GEMM tile geometry ----------------------------------------
// CTA tile: M=256 (2 x 128 halves), N=256, K-chunk=32 (64B rows, SW64)
#define MT 256
#define NT 256
#define KCH 32
#define NCH (GK/KCH)            /* 24 */
#define NSTAGE 3
// per-stage region offsets (bytes from stage base)
#define OA0H 0
#define OA0L 8192
#define OA1H 16384
#define OA1L 24576
#define OBH  32768
#define OBL  49152
#define STAGE_BYTES 65536
#define SM_TILE0 1024
#define GEMM_SMEM (SM_TILE0 + NSTAGE*STAGE_BYTES) /* 197632 */

#if HAS_TCG
// ---------------- tcgen05 helpers (arch-specific pass only) -----------------
__device__ __forceinline__ uint32_t elect1(){
    uint32_t p;
    asm volatile("{\n\t.reg .pred p;\n\telect.sync _|p, 0xFFFFFFFF;\n\tselp.b32 %0, 1, 0, p;\n\t}" : "=r"(p));
    return p;
}
// SW64 descriptor: layout=4, version=1, SBO=32 (512B = 8 rows x 64B), LBO=1
static constexpr uint64_t DESC_BASE_SW64 =
    (uint64_t(4) << 61) | (uint64_t(1) << 46) | (uint64_t(32) << 32) | (uint64_t(1) << 16);
#define MK64(a) (DESC_BASE_SW64 | ((uint64_t)((a) >> 4) & 0x3FFF))
// idesc: F32 accum, BF16 a/b, M=128, N=256
#define GEMM_IDESC 0x8400490u

__device__ __forceinline__ void mma_bf16_ss(uint32_t d, uint64_t a, uint64_t b, uint32_t en){
    asm volatile(
        "{\n\t.reg .pred p;\n\tsetp.ne.u32 p, %3, 0;\n\t"
        "tcgen05.mma.cta_group::1.kind::f16 [%0], %1, %2, %4, {%5,%5,%5,%5}, p;\n\t}"
        :: "r"(d), "l"(a), "l"(b), "r"(en), "r"(GEMM_IDESC), "r"(0u) : "memory");
}
__device__ __forceinline__ void tc_commit(uint32_t mbar){
    asm volatile("tcgen05.commit.cta_group::1.mbarrier::arrive::one.shared::cluster.b64 [%0];"
                 :: "r"(mbar) : "memory");
}
__device__ __forceinline__ void mbar_init(uint32_t mbar, uint32_t cnt){
    asm volatile("mbarrier.init.shared.b64 [%0], %1;" :: "r"(mbar), "r"(cnt) : "memory");
}
__device__ __forceinline__ void mbar_wait(uint32_t mbar, uint32_t parity){
    asm volatile(
        "{\n\t.reg .pred P;\n\tWL_%=:\n\t"
        "mbarrier.try_wait.parity.acquire.cta.shared::cta.b64 P, [%0], %1, 0x989680;\n\t"
        "@P bra.uni WD_%=;\n\tbra.uni WL_%=;\n\tWD_%=:\n\t}"
        :: "r"(mbar), "r"(parity) : "memory");
}
#define FENCE_ASYNC()  asm volatile("fence.proxy.async.shared::cta;" ::: "memory")
#define TC_FENCE_AFTER()  asm volatile("tcgen05.fence::after_thread_sync;" ::: "memory")
#define TC_FENCE_BEFORE() asm volatile("tcgen05.fence::before_thread_sync;" ::: "memory")
#define TC_WAIT_LD() asm volatile("tcgen05.wait::ld.sync.aligned;" ::: "memory")

#define LDTM32(r, addr) \
    asm volatile( \
        "tcgen05.ld.sync.aligned.32x32b.x32.b32 " \
        "{%0, %1, %2, %3, %4, %5, %6, %7, " \
        " %8, %9, %10, %11, %12, %13, %14, %15, " \
        " %16, %17, %18, %19, %20, %21, %22, %23, " \
        " %24, %25, %26, %27, %28, %29, %30, %31}, [%32];" \
        : "=r"((r)[0]),  "=r"((r)[1]),  "=r"((r)[2]),  "=r"((r)[3]), \
          "=r"((r)[4]),  "=r"((r)[5]),  "=r"((r)[6]),  "=r"((r)[7]), \
          "=r"((r)[8]),  "=r"((r)[9]),  "=r"((r)[10]), "=r"((r)[11]), \
          "=r"((r)[12]), "=r"((r)[13]), "=r"((r)[14]), "=r"((r)[15]), \
          "=r"((r)[16]), "=r"((r)[17]), "=r"((r)[18]), "=r"((r)[19]), \
          "=r"((r)[20]), "=r"((r)[21]), "=r"((r)[22]), "=r"((r)[23]), \
          "=r"((r)[24]), "=r"((r)[25]), "=r"((r)[26]), "=r"((r)[27]), \
          "=r"((r)[28]), "=r"((r)[29]), "=r"((r)[30]), "=r"((r)[31]) \
        : "r"(addr))
#endif  // HAS_TCG

// ---------------------------------------------------------------------------
// 3-pass bf16 (hi/lo split) GEMM:  C[M,Ntot] = A[M,GK] * B^T  (B:[Ntot,GK])
// A,B K-major bf16; C fp32 (+optional bias). M%256==0, Ntot%256==0.
// tcgen05 (M=256 split into two TMEM D regions) on arch-specific builds;
// naive correctness-only fallback otherwise (dead code on sm_103a).
// ---------------------------------------------------------------------------
__global__ __launch_bounds__(256) void gemm_bf16_3p(
    const __nv_bfloat16* __restrict__ Ah, const __nv_bfloat16* __restrict__ Al,
    const __nv_bfloat16* __restrict__ Bh, const __nv_bfloat16* __restrict__ Bl,
    float* __restrict__ C, int Ntot, const float* __restrict__ bias)
{
    const int tid = threadIdx.x;
    const int row0 = blockIdx.y * MT;
    const int col0 = blockIdx.x * NT;

#if HAS_TCG
    extern __shared__ char smem[];
    const uint32_t sbase = smem_u32(smem);
    const int wid = tid >> 5;
    const int lane = tid & 31;

    // ---- TMEM alloc (512 cols: D0 at 0, D1 at 256), mbarriers ----
    if (wid == 0) {
        asm volatile("tcgen05.alloc.cta_group::1.sync.aligned.shared::cta.b32 [%0], %1;"
                     :: "r"(sbase), "r"(512u) : "memory");
    }
    if (tid == 0) { mbar_init(sbase + 8, 1); mbar_init(sbase + 16, 1); mbar_init(sbase + 24, 1); }
    __syncthreads();
    uint32_t tmem;
    asm volatile("ld.shared.b32 %0, [%1];" : "=r"(tmem) : "r"(sbase));
    if (wid == 0)
        asm volatile("tcgen05.relinquish_alloc_permit.cta_group::1.sync.aligned;");

    uint32_t leader = 0;
    if (wid == 0) leader = elect1();

    // ---- per-thread load coordinates ----
    // A: 2 threads/row, 32B each (2x16B). B: 1 thread/row, 64B (4x16B).
    const int ar = tid >> 1;
    const int ac = (tid & 1) * 32;
    const int br = tid;
    const char* gA0h = (const char*)Ah + (size_t)(row0 + ar) * (GK*2) + ac;
    const char* gA0l = (const char*)Al + (size_t)(row0 + ar) * (GK*2) + ac;
    const char* gA1h = gA0h + (size_t)128 * (GK*2);
    const char* gA1l = gA0l + (size_t)128 * (GK*2);
    const char* gBh0 = (const char*)Bh + (size_t)(col0 + br) * (GK*2);
    const char* gBl0 = (const char*)Bl + (size_t)(col0 + br) * (GK*2);

    const uint32_t a_so0 = swz64(ar*64 + ac);
    const uint32_t a_so1 = swz64(ar*64 + ac + 16);
    const uint32_t b_so0 = swz64(br*64);
    const uint32_t b_so1 = swz64(br*64 + 16);
    const uint32_t b_so2 = swz64(br*64 + 32);
    const uint32_t b_so3 = swz64(br*64 + 48);

    auto load_chunk = [&](int st, int ch) {
        const int kb = ch * 64;   // bytes along K
        const uint32_t sb = sbase + SM_TILE0 + st*STAGE_BYTES;
        CPA16(sb + OA0H + a_so0, gA0h + kb);      CPA16(sb + OA0H + a_so1, gA0h + kb + 16);
        CPA16(sb + OA0L + a_so0, gA0l + kb);      CPA16(sb + OA0L + a_so1, gA0l + kb + 16);
        CPA16(sb + OA1H + a_so0, gA1h + kb);      CPA16(sb + OA1H + a_so1, gA1h + kb + 16);
        CPA16(sb + OA1L + a_so0, gA1l + kb);      CPA16(sb + OA1L + a_so1, gA1l + kb + 16);
        CPA16(sb + OBH + b_so0, gBh0 + kb);       CPA16(sb + OBH + b_so1, gBh0 + kb + 16);
        CPA16(sb + OBH + b_so2, gBh0 + kb + 32);  CPA16(sb + OBH + b_so3, gBh0 + kb + 48);
        CPA16(sb + OBL + b_so0, gBl0 + kb);       CPA16(sb + OBL + b_so1, gBl0 + kb + 16);
        CPA16(sb + OBL + b_so2, gBl0 + kb + 32);  CPA16(sb + OBL + b_so3, gBl0 + kb + 48);
    };

    // ---- prologue: 2 chunks in flight ----
    load_chunk(0, 0); CPA_COMMIT();
    load_chunk(1, 1); CPA_COMMIT();

    int p0 = 0, p1 = 0, p2 = 0;
    uint32_t first = 0;
    const uint32_t tm0 = tmem, tm1 = tmem + 256;

    for (int ch = 0; ch < NCH; ch++) {
        const int b = ch % 3;
        CPA_WAIT1();           // oldest pending group (this chunk's) done
        __syncthreads();
        FENCE_ASYNC();

        if (leader) {
            const uint32_t sb = sbase + SM_TILE0 + b*STAGE_BYTES;
            const uint64_t dA0h = MK64(sb + OA0H), dA0l = MK64(sb + OA0L);
            const uint64_t dA1h = MK64(sb + OA1H), dA1l = MK64(sb + OA1L);
            const uint64_t dBh  = MK64(sb + OBH),  dBl  = MK64(sb + OBL);
            #pragma unroll
            for (int k = 0; k < 2; k++) {
                const uint64_t o = k*2;
                mma_bf16_ss(tm0, dA0h + o, dBh + o, first);
                mma_bf16_ss(tm1, dA1h + o, dBh + o, first);
                first = 1;
                mma_bf16_ss(tm0, dA0h + o, dBl + o, 1);
                mma_bf16_ss(tm1, dA1h + o, dBl + o, 1);
                mma_bf16_ss(tm0, dA0l + o, dBh + o, 1);
                mma_bf16_ss(tm1, dA1l + o, dBh + o, 1);
            }
            tc_commit(sbase + 8 + b*8);
        }

        if (ch + 2 < NCH) {
            const int nb = (ch + 2) % 3;
            if (ch >= 1) {   // MMAs of chunk ch-1 (same buffer) must be done
                if      (nb == 0) { mbar_wait(sbase + 8,  p0); p0 ^= 1; }
                else if (nb == 1) { mbar_wait(sbase + 16, p1); p1 ^= 1; }
                else              { mbar_wait(sbase + 24, p2); p2 ^= 1; }
            }
            load_chunk(nb, ch + 2);
            CPA_COMMIT();
        }
    }

    // last chunk (23) committed on stage 2; wait covers all prior MMAs
    mbar_wait(sbase + 24, p2);
    TC_FENCE_AFTER();

    // ---- epilogue: 8 warps; warps 0-3 -> D0 (rows row0..+128),
    //                warps 4-7 -> D1 (rows row0+128..+256) ----
    {
        const int mh = wid >> 2;
        const int r = row0 + mh*128 + (wid & 3)*32 + lane;
        const uint32_t tb = tmem + mh*256;
        float* crow = C + (size_t)r * Ntot;
        #pragma unroll
        for (int chk = 0; chk < 8; chk++) {
            uint32_t regs[32];
            LDTM32(regs, tb + chk*32);
            TC_WAIT_LD();
            const int c0 = col0 + chk*32;
            #pragma unroll
            for (int j = 0; j < 32; j += 4) {
                float4 v;
                v.x = __uint_as_float(regs[j+0]);
                v.y = __uint_as_float(regs[j+1]);
                v.z = __uint_as_float(regs[j+2]);
                v.w = __uint_as_float(regs[j+3]);
                if (bias) {
                    v.x += bias[c0+j+0]; v.y += bias[c0+j+1];
                    v.z += bias[c0+j+2]; v.w += bias[c0+j+3];
                }
                *(float4*)(crow + c0 + j) = v;
            }
        }
        TC_FENCE_BEFORE();
    }
    __syncthreads();
    if (tid == 0) {
        asm volatile("mbarrier.inval.shared.b64 [%0];" :: "r"(sbase + 8) : "memory");
        asm volatile("mbarrier.inval.shared.b64 [%0];" :: "r"(sbase + 16) : "memory");
        asm volatile("mbarrier.inval.shared.b64 [%0];" :: "r"(sbase + 24) : "memory");
    }
    __syncthreads();
    if (wid == 0) {
        asm volatile("tcgen05.dealloc.cta_group::1.sync.aligned.b32 %0, %1;"
                     :: "r"(tmem), "r"(512u));
    }

#else
    // ---- correctness-only fallback (dead code on sm_103a cubin) ----
    for (int idx = tid; idx < MT*NT; idx += 256) {
        const int r = row0 + idx / NT;
        const int c = col0 + idx % NT;
        float s = bias ? bias[c] : 0.f;
        const __nv_bfloat16* arh = Ah + (size_t)r * GK;
        const __nv_bfloat16* arl = Al + (size_t)r * GK;
        const __nv_bfloat16* brh = Bh + (size_t)c * GK;
        const __nv_bfloat16* brl = Bl + (size_t)c * GK;
        for (int k = 0; k < GK; k++) {
            float av = __bfloat162float(arh[k]) + __bfloat162float(arl[k]);
            float bv = __bfloat162float(brh[k]) + __bfloat162float(brl[k]);
            s = fmaf(av, bv, s);
        }
        C[(size_t)r * Ntot + c] = s;
    }
#endif
}

// ---------------------------------------------------------------------------
// fp32 -> bf16 hi/lo split (elementwise)
// ---------------------------------------------------------------------------
__global__ __launch_bounds__(256) void split_kernel(
    const float* __restrict__ in, __nv_bfloat16* __restrict__ h,
    __nv_bfloat16* __restrict__ l, size_t n4)
{
    size_t i = (size_t)blockIdx.x * blockDim.x + threadIdx.x;
    if (i >= n4) return;
    float4 v = ((const float4*)in)[i];
    __nv_bfloat16 h0 = __float2bfloat16(v.x), h1 = __float2bfloat16(v.y);
    __nv_bfloat16 h2 = __float2bfloat16(v.z), h3 = __float2bfloat16(v.w);
    __nv_bfloat16 l0 = __float2bfloat16(v.x - __bfloat162float(h0));
    __nv_bfloat16 l1 = __float2bfloat16(v.y - __bfloat162float(h1));
    __nv_bfloat16 l2 = __float2bfloat16(v.z - __bfloat162float(h2));
    __nv_bfloat16 l3 = __float2bfloat16(v.w - __bfloat162float(h3));
    ((__nv_bfloat162*)h)[2*i]   = __halves2bfloat162(h0, h1);
    ((__nv_bfloat162*)h)[2*i+1] = __halves2bfloat162(h2, h3);
    ((__nv_bfloat162*)l)[2*i]   = __halves2bfloat162(l0, l1);
    ((__nv_bfloat162*)l)[2*i+1] = __halves2bfloat162(l2, l3);
}

// ---------------------------------------------------------------------------
// W [K,N] fp32 -> transposed bf16 hi/lo [N,K]
// ---------------------------------------------------------------------------
__global__ __launch_bounds__(256) void transpose_split(
    const float* __restrict__ W, __nv_bfloat16* __restrict__ h,
    __nv_bfloat16* __restrict__ l, int K, int N)
{
    __shared__ float t[32][33];
    const int n0 = blockIdx.x * 32, k0 = blockIdx.y * 32;
    const int tx = threadIdx.x & 31, ty = threadIdx.x >> 5;
    #pragma unroll
    for (int i = ty; i < 32; i += 8)
        t[i][tx] = W[(size_t)(k0 + i) * N + n0 + tx];
    __syncthreads();
    #pragma unroll
    for (int i = ty; i < 32; i += 8) {
        float v = t[tx][i];
        __nv_bfloat16 hv = __float2bfloat16(v);
        __nv_bfloat16 lv = __float2bfloat16(v - __bfloat162float(hv));
        h[(size_t)(n0 + i) * K + k0 + tx] = hv;
        l[(size_t)(n0 + i) * K + k0 + tx] = lv;
    }
}

// ---------------------------------------------------------------------------
// fused norms + cross-cov + temperature + softmax (one CTA per (b,h))
// ---------------------------------------------------------------------------
__global__ __launch_bounds__(256) void attn_kernel(const float* __restrict__ temp)
{
    const int bh = blockIdx.x;
    const int b  = bh / Hh, h = bh % Hh;
    const int tid = threadIdx.x;
    const int tx = tid & 15, ty = tid >> 4;

    __shared__ float Qs[64][68];
    __shared__ float Ks[64][68];
    __shared__ float ps[256];
    __shared__ float normQ[64], normK[64];

    const size_t rowbase = (size_t)b * Nn;
    const int qoff = h * dh;
    const int koff = Dd + h * dh;

    float acc[4][4];
    #pragma unroll
    for (int i = 0; i < 4; i++)
        #pragma unroll
        for (int j = 0; j < 4; j++) acc[i][j] = 0.f;
    float pssq = 0.f;

    const int lr = tid >> 4;
    const int lc = (tid & 15) << 2;
    const int scol  = tid & 127;
    const int shalf = (tid >> 7) * 32;

    for (int n0 = 0; n0 < Nn; n0 += 64) {
        #pragma unroll
        for (int pp = 0; pp < 64; pp += 16) {
            const size_t grow = (rowbase + n0 + pp + lr) * QKVC;
            *(float4*)&Qs[pp + lr][lc] = *(const float4*)(g_qkv + grow + qoff + lc);
            *(float4*)&Ks[pp + lr][lc] = *(const float4*)(g_qkv + grow + koff + lc);
        }
        __syncthreads();
        #pragma unroll 4
        for (int n = 0; n < 64; n++) {
            float rq[4], rk[4];
            *(float4*)rq = *(const float4*)&Qs[n][tx * 4];
            *(float4*)rk = *(const float4*)&Ks[n][ty * 4];
            #pragma unroll
            for (int i = 0; i < 4; i++)
                #pragma unroll
                for (int j = 0; j < 4; j++)
                    acc[i][j] = fmaf(rk[i], rq[j], acc[i][j]);
        }
        {
            const float* colp = (scol < 64) ? &Qs[0][scol] : &Ks[0][scol - 64];
            #pragma unroll
            for (int n = 0; n < 32; n++) {
                const float v = colp[(size_t)(shalf + n) * 68];
                pssq = fmaf(v, v, pssq);
            }
        }
        __syncthreads();
    }

    ps[tid] = pssq;
    __syncthreads();
    if (tid < 128) {
        const float s  = ps[tid] + ps[tid + 128];
        const float nv = fmaxf(sqrtf(s), 1e-12f);
        if (tid < 64) normQ[tid] = nv; else normK[tid - 64] = nv;
    }
    __syncthreads();

    const float tv = temp[h];
    #pragma unroll
    for (int i = 0; i < 4; i++)
        #pragma unroll
        for (int j = 0; j < 4; j++)
            Qs[ty * 4 + i][tx * 4 + j] =
                acc[i][j] * tv / (normK[ty * 4 + i] * normQ[tx * 4 + j]);
    __syncthreads();

    if (tid < 64) {
        const int p = tid;
        float m = -1e30f;
        for (int q = 0; q < 64; q++) m = fmaxf(m, Qs[p][q]);
        float s = 0.f;
        for (int q = 0; q < 64; q++) s += expf(Qs[p][q] - m);
        const float inv = 1.f / s;
        float* op = g_attn + (size_t)bh * 4096 + p * 64;
        for (int q = 0; q < 64; q++) op[q] = expf(Qs[p][q] - m) * inv;
    }
}

// ---------------------------------------------------------------------------
// out[b,h,n,q] = sum_p v[n,p] attn[p,q]  -> written directly as bf16 hi/lo
// ---------------------------------------------------------------------------
__global__ __launch_bounds__(256) void av_kernel()
{
    const int bh = blockIdx.x;
    const int nt = blockIdx.y;
    const int b  = bh / Hh, h = bh % Hh;
    const int tid = threadIdx.x;
    const int tx = tid & 15, ty = tid >> 4;

    __shared__ float At[64][68];
    __shared__ float Vs[64][68];

    {
        const float* ap = g_attn + (size_t)bh * 4096;
        #pragma unroll
        for (int pp = 0; pp < 4; pp++) {
            const int idx = pp * 1024 + tid * 4;
            *(float4*)&At[idx >> 6][idx & 63] = *(const float4*)(ap + idx);
        }
    }
    const int lr = tid >> 4, lc = (tid & 15) << 2;
    const int voff = 2 * Dd + h * dh;
    const size_t rowbase = (size_t)b * Nn + nt * 64;
    #pragma unroll
    for (int pp = 0; pp < 64; pp += 16)
        *(float4*)&Vs[pp + lr][lc] =
            *(const float4*)(g_qkv + (rowbase + pp + lr) * QKVC + voff + lc);
    __syncthreads();

    float acc[4][4];
    #pragma unroll
    for (int i = 0; i < 4; i++)
        #pragma unroll
        for (int j = 0; j < 4; j++) acc[i][j] = 0.f;

    #pragma unroll 8
    for (int p = 0; p < 64; p++) {
        float ra[4];
        *(float4*)ra = *(const float4*)&At[p][tx * 4];
        float rv[4];
        #pragma unroll
        for (int i = 0; i < 4; i++) rv[i] = Vs[ty * 4 + i][p];
        #pragma unroll
        for (int i = 0; i < 4; i++)
            #pragma unroll
            for (int j = 0; j < 4; j++)
                acc[i][j] = fmaf(rv[i], ra[j], acc[i][j]);
    }

    #pragma unroll
    for (int i = 0; i < 4; i++) {
        const size_t r = rowbase + ty * 4 + i;
        const size_t off = r * Dd + h * dh + tx * 4;
        __nv_bfloat16 hv[4], lv[4];
        #pragma unroll
        for (int j = 0; j < 4; j++) {
            hv[j] = __float2bfloat16(acc[i][j]);
            lv[j] = __float2bfloat16(acc[i][j] - __bfloat162float(hv[j]));
        }
        *(__nv_bfloat162*)(g_oh + off)     = __halves2bfloat162(hv[0], hv[1]);
        *(__nv_bfloat162*)(g_oh + off + 2) = __halves2bfloat162(hv[2], hv[3]);
        *(__nv_bfloat162*)(g_ol + off)     = __halves2bfloat162(lv[0], lv[1]);
        *(__nv_bfloat162*)(g_ol + off + 2) = __halves2bfloat162(lv[2], lv[3]);
    }
}

// ---------------------------------------------------------------------------
extern "C" void kernel_launch(void* const* d_in, const int* in_sizes, int n_in,
                              void* d_out, int out_size)
{
    const float* x     = (const float*)d_in[0];
    const float* Wqkv  = (const float*)d_in[1];
    const float* temp  = (const float*)d_in[2];
    const float* Wout  = (const float*)d_in[3];
    const float* bout  = (const float*)d_in[4];
    float* out = (float*)d_out;

    float *qkv;
    __nv_bfloat16 *xh, *xl, *wh, *wl, *woh, *wol, *oh, *ol;
    cudaGetSymbolAddress((void**)&qkv,   g_qkv);
    cudaGetSymbolAddress((void**)&xh,  g_xh);  cudaGetSymbolAddress((void**)&xl,  g_xl);
    cudaGetSymbolAddress((void**)&wh,  g_wh);  cudaGetSymbolAddress((void**)&wl,  g_wl);
    cudaGetSymbolAddress((void**)&woh, g_woh); cudaGetSymbolAddress((void**)&wol, g_wol);
    cudaGetSymbolAddress((void**)&oh,  g_oh);  cudaGetSymbolAddress((void**)&ol,  g_ol);

    cudaFuncSetAttribute(gemm_bf16_3p, cudaFuncAttributeMaxDynamicSharedMemorySize, GEMM_SMEM);

    // 1) split inputs to bf16 hi/lo
    {
        size_t n4 = (size_t)Mrows * Dd / 4;
        split_kernel<<<(unsigned)((n4 + 255) / 256), 256>>>(x, xh, xl, n4);
    }
    transpose_split<<<dim3(QKVC/32, Dd/32), 256>>>(Wqkv, wh, wl, Dd, QKVC);
    transpose_split<<<dim3(Dd/32,  Dd/32), 256>>>(Wout, woh, wol, Dd, Dd);

    // 2) qkv = x @ Wqkv  (tcgen05, 3-pass bf16, 3-stage pipeline, M-tile 256)
    gemm_bf16_3p<<<dim3(QKVC/NT, Mrows/MT), 256, GEMM_SMEM>>>(xh, xl, wh, wl, qkv, QKVC, nullptr);

    // 3) fused normalize + cross-covariance + temperature + softmax
    attn_kernel<<<dim3(Bc * Hh), 256>>>(temp);

    // 4) out = v @ attn  (writes bf16 hi/lo directly — split fused)
    av_kernel<<<dim3(Bc * Hh, Nn / 64), 256>>>();

    // 5) final projection + bias (tcgen05)
    gemm_bf16_3p<<<dim3(Dd/NT, Mrows/MT), 256, GEMM_SMEM>>>(oh, ol, woh, wol, out, Dd, bout);
}